// round 11
// baseline (speedup 1.0000x reference)
#include <cuda_runtime.h>
#include <cuda_fp16.h>

#define Bq 4
#define Cc 32
#define Tt 1024
#define Uu 32
#define Hh 128
#define NCHK 4                  // 256-j chunks

// Scratch — device globals (no allocations allowed).
__device__ float    g_qp[Bq * Tt * Uu];            // q + bh, (B,T,U) f32
__device__ unsigned g_kh_u[Bq * Uu * Tt / 2];      // k as f16, (B,U,T)
__device__ unsigned g_xh_u[Bq * Cc * Tt / 2];      // x as f16, (B,C,T)

__device__ __forceinline__ __half2 tanh2(__half2 x) {
    unsigned xi = *reinterpret_cast<unsigned*>(&x), ri;
    asm("tanh.approx.f16x2 %0, %1;" : "=r"(ri) : "r"(xi));
    return *reinterpret_cast<__half2*>(&ri);
}
__device__ __forceinline__ __half2 u2h2(unsigned u) { return *reinterpret_cast<__half2*>(&u); }
__device__ __forceinline__ unsigned h22u(__half2 h) { return *reinterpret_cast<unsigned*>(&h); }

// ---------------------------------------------------------------------------
// k_prep (R8, proven): 8 tokens/block, grid = B*(T/8) = 512, 256 threads.
// ---------------------------------------------------------------------------
__global__ void __launch_bounds__(256) k_prep(const float* __restrict__ x,
                                              const float* __restrict__ Wt,
                                              const float* __restrict__ Wx,
                                              const float* __restrict__ bh) {
    __shared__ float xs[Cc][9];
    __shared__ float Wts[Cc][33];
    __shared__ float Wxs[Cc][33];
    __shared__ float bhs[Uu];
    __shared__ __half kts[Uu][10];

    int b  = blockIdx.x >> 7;
    int t0 = (blockIdx.x & 127) * 8;
    int tid = threadIdx.x, w = tid >> 5, lane = tid & 31;

    {
        int c = tid >> 3, tl = tid & 7;
        xs[c][tl] = x[(size_t)b * Cc * Tt + (size_t)c * Tt + t0 + tl];
    }
    for (int i = tid; i < Cc * Uu; i += 256) {
        int c = i >> 5, u = i & 31;
        Wts[c][u] = Wt[i];
        Wxs[c][u] = Wx[i];
    }
    if (tid < Uu) bhs[tid] = bh[tid];
    __syncthreads();

    {
        int tl = w, u = lane;
        float accq = bhs[u], acck = 0.f;
        #pragma unroll
        for (int c = 0; c < Cc; c++) {
            float xv = xs[c][tl];
            accq += xv * Wts[c][u];
            acck += xv * Wxs[c][u];
        }
        g_qp[((size_t)b * Tt + t0 + tl) * Uu + u] = accq;
        kts[u][tl] = __float2half(acck);
    }
    __syncthreads();

    if (tid < 128) {
        int r = tid >> 2, g = tid & 3;
        __half* kh = (__half*)g_kh_u;
        __half2 kv = __halves2half2(kts[r][2 * g], kts[r][2 * g + 1]);
        *(unsigned*)(kh + ((size_t)b * Uu + r) * Tt + t0 + 2 * g) = h22u(kv);
        __half* xh = (__half*)g_xh_u;
        __half2 xv = __floats2half2_rn(xs[r][2 * g], xs[r][2 * g + 1]);
        *(unsigned*)(xh + ((size_t)b * Cc + r) * Tt + t0 + 2 * g) = h22u(xv);
    }
}

// ---------------------------------------------------------------------------
// k_fused v2: 8 rows/block, 256 threads, warp w = row w. grid = B*(T/8) = 512.
// scores + softmax + v + a-write + LN1 + FF + LN2, e-tile in smem.
// ---------------------------------------------------------------------------
#define OFF_K    0                           // half2 khs[32][128] 16384 | x-tile | W1T(0..16512)
#define OFF_E    16384                       // half2 es[8][512]   16384 | W2p(16512..33024)
#define OFF_WA   32768                       // half2 was[32]        128 (dead by FF)
#define OFF_Q    32896                       // float qsm[8*33]     1056 (dead by FF)
#define OFF_YS   33952                       // float ys[8*33]      1056
#define OFF_H1   35008                       // float h1s[8*132]    4224
#define OFF_B1   39232                       // float b1s[128]       512
#define OFF_B2   39744                       // float b2s[32]        128
#define OFF_G2   39872                       // float g2s[32]        128
#define OFF_BE2  40000                       // float be2s[32]       128
#define SMEM_FUSED 40128

__global__ void __launch_bounds__(256) k_fused(const float* __restrict__ x,
                                               float* __restrict__ a_out,
                                               const float* __restrict__ Wa,
                                               const float* __restrict__ ba,
                                               const float* __restrict__ g1,
                                               const float* __restrict__ be1,
                                               const float* __restrict__ W1,
                                               const float* __restrict__ b1,
                                               const float* __restrict__ W2,
                                               const float* __restrict__ b2,
                                               const float* __restrict__ g2,
                                               const float* __restrict__ be2,
                                               float* __restrict__ y2) {
    extern __shared__ char dyn[];
    __half2* khs  = (__half2*)(dyn + OFF_K);    // [32][128]
    __half2* es   = (__half2*)(dyn + OFF_E);    // [8][512]
    __half2* was  = (__half2*)(dyn + OFF_WA);
    float* qsm  = (float*)(dyn + OFF_Q);
    float* W1T  = (float*)(dyn + OFF_K);        // FF overlay
    float* W2p  = (float*)(dyn + OFF_K + 16512);
    float* ys   = (float*)(dyn + OFF_YS);
    float* h1s  = (float*)(dyn + OFF_H1);
    float* b1s  = (float*)(dyn + OFF_B1);
    float* b2s  = (float*)(dyn + OFF_B2);
    float* g2s  = (float*)(dyn + OFF_G2);
    float* be2s = (float*)(dyn + OFF_BE2);

    int b  = blockIdx.x >> 7;
    int t0 = (blockIdx.x & 127) * 8;
    int tid = threadIdx.x, w = tid >> 5, lane = tid & 31;
    int t = t0 + w;                               // this warp's row/token
    size_t row = (size_t)b * Tt + t;

    // ---- staging ----
    for (int i = tid; i < 8 * Uu; i += 256) {
        int r = i >> 5, u = i & 31;
        qsm[r * 33 + u] = g_qp[((size_t)b * Tt + t0 + r) * Uu + u];
    }
    if (tid < Uu) was[tid] = __float2half2_rn(Wa[tid]);
    if (tid < Hh) b1s[tid] = b1[tid];
    if (tid < Cc) { b2s[tid] = b2[tid]; g2s[tid] = g2[tid]; be2s[tid] = be2[tid]; }
    __syncthreads();

    __half2 q2[Uu];
    #pragma unroll
    for (int u = 0; u < Uu; u++) q2[u] = __float2half2_rn(qsm[w * 33 + u]);

    __half2 ba2  = __float2half2_rn(ba[0]);
    __half2 m2   = __float2half2_rn(-60000.f);
    __half2 z2   = __float2half2_rn(0.f);
    __half2 one2 = __float2half2_rn(1.f);
    __half2 ca2  = __float2half2_rn(-1.f / 3.f);
    __half2 cb2  = __float2half2_rn(2.f / 15.f);

    const uint4* kb4 = (const uint4*)g_kh_u + (size_t)b * (Uu * Tt / 8);

    // ---- Phase A: e for row w, chunk by chunk, into smem es ----
    for (int ch = 0; ch < NCHK; ch++) {
        __syncthreads();
        #pragma unroll
        for (int k = 0; k < 4; k++) {
            int idx = tid + k * 256;
            int r = idx >> 5, g = idx & 31;
            ((uint4*)khs)[idx] = kb4[r * 128 + ch * 32 + g];
        }
        __syncthreads();

        #pragma unroll
        for (int jt = 0; jt < 4; jt++) {
            int pj = jt * 32 + lane;
            __half2 acc0 = z2, acc1 = z2;
            #pragma unroll
            for (int u = 0; u < Uu; u += 2) {
                // even u: MUFU tanh
                __half2 xm = __hadd2(q2[u], khs[u * 128 + pj]);
                acc0 = __hfma2(was[u], tanh2(xm), acc0);
                // odd u: poly on FMA pipe
                __half2 xp = __hadd2(q2[u + 1], khs[(u + 1) * 128 + pj]);
                __half2 x2 = __hmul2(xp, xp);
                __half2 tp = __hfma2(x2, cb2, ca2);
                tp = __hfma2(x2, tp, one2);
                acc1 = __hfma2(was[u + 1], __hmul2(xp, tp), acc1);
            }
            __half2 e2 = __hadd2(__hadd2(acc0, acc1), ba2);
            m2 = __hmax2(m2, e2);
            es[w * 512 + ch * 128 + pj] = e2;
        }
    }

    float mv = fmaxf(__low2float(m2), __high2float(m2));
    #pragma unroll
    for (int off = 16; off; off >>= 1)
        mv = fmaxf(mv, __shfl_xor_sync(0xffffffffu, mv, off));

    // ---- Phase B: s + unnormalized v (x-chunks overlay khs) ----
    float s = 0.f;
    __half2 v2[Cc];
    #pragma unroll
    for (int c = 0; c < Cc; c++) v2[c] = z2;

    const uint4* xsrc = (const uint4*)g_xh_u + (size_t)b * (Cc * Tt / 8);
    __half2* xh2s = khs;   // overlay

    for (int ch = 0; ch < NCHK; ch++) {
        __syncthreads();
        #pragma unroll
        for (int k = 0; k < 4; k++) {
            int idx = tid + k * 256;
            int r = idx >> 5, g = idx & 31;
            ((uint4*)xh2s)[idx] = xsrc[r * 128 + ch * 32 + g];
        }
        __syncthreads();

        uint4 ev = ((const uint4*)(es + w * 512))[ch * 32 + lane];
        unsigned eu[4] = {ev.x, ev.y, ev.z, ev.w};
        __half2 p[4];
        #pragma unroll
        for (int r = 0; r < 4; r++) {
            float2 f = __half22float2(u2h2(eu[r]));
            float px = __expf(f.x), py = __expf(f.y);
            s += px + py;
            p[r] = __floats2half2_rn(px, py);
        }
        #pragma unroll
        for (int c = 0; c < Cc; c++) {
            uint4 xv = ((const uint4*)(xh2s + c * 128))[lane];
            v2[c] = __hfma2(p[0], u2h2(xv.x), v2[c]);
            v2[c] = __hfma2(p[1], u2h2(xv.y), v2[c]);
            v2[c] = __hfma2(p[2], u2h2(xv.z), v2[c]);
            v2[c] = __hfma2(p[3], u2h2(xv.w), v2[c]);
        }
    }

    float vf[Cc];
    #pragma unroll
    for (int c = 0; c < Cc; c++) {
        float2 f = __half22float2(v2[c]); vf[c] = f.x + f.y;
    }
    #pragma unroll
    for (int off = 16; off; off >>= 1)
        s += __shfl_xor_sync(0xffffffffu, s, off);
    float inv = 1.f / (s + 1e-5f * __expf(mv));

    // ---- Phase C: normalized a straight from smem e ----
    {
        float* arow = a_out + row * Tt;
        const unsigned* esw = (const unsigned*)(es + w * 512);
        #pragma unroll
        for (int q = 0; q < 16; q++) {
            int idx = q * 32 + lane;
            float2 f = __half22float2(u2h2(esw[idx]));
            ((float2*)arow)[idx] = make_float2(__expf(f.x) * inv, __expf(f.y) * inv);
        }
    }

    float mine = 0.f;
    #pragma unroll
    for (int c = 0; c < Cc; c++) {
        float tc = vf[c];
        #pragma unroll
        for (int off = 16; off; off >>= 1)
            tc += __shfl_xor_sync(0xffffffffu, tc, off);
        if (lane == c) mine = tc;
    }

    __syncthreads();   // es/khs dead -> FF weight overlay begins

    for (int i = tid; i < Hh * Cc; i += 256) {
        int h = i >> 5, c = i & 31;
        W1T[c * 129 + h] = W1[i];                 // W1 (H,C) row-major
        int c2 = i >> 7, h2 = i & 127;
        W2p[c2 * 129 + h2] = W2[i];               // W2 (C,H) row-major
    }

    // ---- LN1 (lane = channel) -> ys ----
    {
        float xres = x[(size_t)b * Cc * Tt + (size_t)lane * Tt + t];
        float z = xres + mine * inv;
        float sum = z;
        #pragma unroll
        for (int off = 16; off; off >>= 1)
            sum += __shfl_xor_sync(0xffffffffu, sum, off);
        float mean = sum * (1.f / Cc);
        float d = z - mean;
        float vv = d * d;
        #pragma unroll
        for (int off = 16; off; off >>= 1)
            vv += __shfl_xor_sync(0xffffffffu, vv, off);
        float rstd = rsqrtf(vv * (1.f / Cc) + 1e-14f);
        ys[w * 33 + lane] = d * rstd * g1[lane] + be1[lane];
    }
    __syncthreads();   // weights staged + ys ready

    // ---- FF (warp w = token w) ----
    float acc[4];
    #pragma unroll
    for (int k = 0; k < 4; k++) acc[k] = b1s[lane + 32 * k];
    #pragma unroll
    for (int c = 0; c < Cc; c++) {
        float yv = ys[w * 33 + c];
        #pragma unroll
        for (int k = 0; k < 4; k++)
            acc[k] += yv * W1T[c * 129 + lane + 32 * k];
    }
    #pragma unroll
    for (int k = 0; k < 4; k++)
        h1s[w * 132 + lane + 32 * k] = fmaxf(acc[k], 0.f);
    __syncwarp();

    float a2 = 0.f;
    #pragma unroll 4
    for (int h = 0; h < Hh; h++)
        a2 += h1s[w * 132 + h] * W2p[lane * 129 + h];

    {
        float z = ys[w * 33 + lane] + a2 + b2s[lane];
        float sum = z;
        #pragma unroll
        for (int off = 16; off; off >>= 1)
            sum += __shfl_xor_sync(0xffffffffu, sum, off);
        float mean = sum * (1.f / Cc);
        float d = z - mean;
        float vv = d * d;
        #pragma unroll
        for (int off = 16; off; off >>= 1)
            vv += __shfl_xor_sync(0xffffffffu, vv, off);
        float rstd = rsqrtf(vv * (1.f / Cc) + 1e-14f);
        y2[(size_t)b * Cc * Tt + (size_t)lane * Tt + t] = d * rstd * g2s[lane] + be2s[lane];
    }
}

// ---------------------------------------------------------------------------
extern "C" void kernel_launch(void* const* d_in, const int* in_sizes, int n_in,
                              void* d_out, int out_size) {
    (void)in_sizes; (void)n_in; (void)out_size;
    const float* x   = (const float*)d_in[0];
    const float* Wt  = (const float*)d_in[1];
    const float* Wx  = (const float*)d_in[2];
    const float* bh  = (const float*)d_in[3];
    const float* Wa  = (const float*)d_in[4];
    const float* ba  = (const float*)d_in[5];
    const float* g1  = (const float*)d_in[6];
    const float* be1 = (const float*)d_in[7];
    const float* W1  = (const float*)d_in[8];
    const float* b1  = (const float*)d_in[9];
    const float* W2  = (const float*)d_in[10];
    const float* b2  = (const float*)d_in[11];
    const float* g2  = (const float*)d_in[12];
    const float* be2 = (const float*)d_in[13];

    float* out = (float*)d_out;
    float* y2  = out;                    // (B,C,T) = 131072 floats
    float* a   = out + Bq * Cc * Tt;     // (B,T,T) = 4194304 floats

    cudaFuncSetAttribute(k_fused, cudaFuncAttributeMaxDynamicSharedMemorySize, SMEM_FUSED);

    k_prep <<<Bq * (Tt / 8), 256>>>(x, Wt, Wx, bh);
    k_fused<<<Bq * (Tt / 8), 256, SMEM_FUSED>>>(x, a, Wa, ba, g1, be1,
                                                W1, b1, W2, b2, g2, be2, y2);
}